// round 9
// baseline (speedup 1.0000x reference)
#include <cuda_runtime.h>
#include <cuda_bf16.h>
#include <math.h>
#include <stdint.h>

// Problem constants
#define BB 16
#define CC 8
#define LL 16384
#define RR 32

#define TM 512                 // t rows per CTA tile
#define NTILES 4096            // c-major: c=g>>9, b=(g>>5)&15, seg=g&31
#define NBLOCKS 152
#define NTHREADS 256           // 8 warps, each warp: m64 x n64

#define B8STRIDE 272           // bytes per B row (256 + 16 pad) -> 68 words

// SMEM offsets (bytes)
#define B8H_OFF 0                        // B_hi int8: 64 x 272 = 17408
#define B8L_OFF 17408                    // B_lo int8
#define XW_OFF  34816                    // fp32 window: 776 floats (3104 B)
#define H0_OFF  37920                    // packed int8 hi, 200 words
#define L0_OFF  38720                    // packed int8 lo
#define XHS_OFF 39520                    // 4 staggered hi arrays, 200 words each
#define XLS_OFF 42720                    // 4 staggered lo arrays
#define FS_OFF  45920                    // per-n filter scales, 64 floats
#define WM_OFF  46176                    // per-warp |x| maxes, 8 floats
#define SG_OFF  46208                    // next-tile id
#define SMEM_BYTES (SG_OFF + 16)

// Precomputed int8 Gabor bank + per-column scales
__device__ __align__(16) signed char g_b8h[CC][64 * B8STRIDE];
__device__ __align__(16) signed char g_b8l[CC][64 * B8STRIDE];
__device__ float g_fs[CC][64];
__device__ unsigned int g_counter;

// One block (256 threads) per filter f: full-tap max reduce + int8 quantize
__global__ void bank_kernel(const float* __restrict__ kV, const float* __restrict__ sV) {
    int f = blockIdx.x;      // 0..255
    int w = threadIdx.x;     // 0..255
    if (f == 0 && w == 0) g_counter = 0;

    float k = kV[f], s = sV[f];
    float phase = ((float)(-2.0 * M_PI / 256.0) * k) * (float)w;
    double sp, cp;
    sincos((double)phase, &sp, &cp);
    float nm = (float)w - 128.0f;
    float s2v = s * s;
    float inv2s2 = 1.0f / (2.0f * s2v);
    float coef = 1.0f / sqrtf(2.0f * (float)M_PI * s2v);
    float gauss = coef * expf(-inv2s2 * nm * nm);
    float fre = (float)cp * gauss, fim = (float)sp * gauss;

    __shared__ float red[256];
    __shared__ float smx[2];
    red[w] = fabsf(fre);
    __syncthreads();
    for (int st = 128; st; st >>= 1) {
        if (w < st) red[w] = fmaxf(red[w], red[w + st]);
        __syncthreads();
    }
    if (w == 0) smx[0] = red[0];
    __syncthreads();
    red[w] = fabsf(fim);
    __syncthreads();
    for (int st = 128; st; st >>= 1) {
        if (w < st) red[w] = fmaxf(red[w], red[w + st]);
        __syncthreads();
    }
    if (w == 0) smx[1] = red[0];
    __syncthreads();

    float Sre = fmaxf(smx[0], 1e-30f) * (1.0f / 127.0f);
    float Sim = fmaxf(smx[1], 1e-30f) * (1.0f / 127.0f);

    int c = f >> 5, j = f & 31, r = 31 - j;   // reference reverses R

    float Fr = fre / Sre;
    int H = __float2int_rn(Fr);
    int L = __float2int_rn((Fr - (float)H) * 256.0f);
    L = max(-127, min(127, L));
    g_b8h[c][(2 * r) * B8STRIDE + w] = (signed char)H;
    g_b8l[c][(2 * r) * B8STRIDE + w] = (signed char)L;

    float Fi = fim / Sim;
    H = __float2int_rn(Fi);
    L = __float2int_rn((Fi - (float)H) * 256.0f);
    L = max(-127, min(127, L));
    g_b8h[c][(2 * r + 1) * B8STRIDE + w] = (signed char)H;
    g_b8l[c][(2 * r + 1) * B8STRIDE + w] = (signed char)L;

    if (w == 0) {
        g_fs[c][2 * r] = Sre;
        g_fs[c][2 * r + 1] = Sim;
    }
}

__device__ __forceinline__ void imma(int* d,
                                     uint32_t a0, uint32_t a1, uint32_t a2, uint32_t a3,
                                     uint32_t b0, uint32_t b1) {
    asm volatile(
        "mma.sync.aligned.m16n8k32.row.col.s32.s8.s8.s32 "
        "{%0,%1,%2,%3}, {%4,%5,%6,%7}, {%8,%9}, {%0,%1,%2,%3};"
        : "+r"(d[0]), "+r"(d[1]), "+r"(d[2]), "+r"(d[3])
        : "r"(a0), "r"(a1), "r"(a2), "r"(a3), "r"(b0), "r"(b1));
}

// One dense int8 GEMM pass: A from staggered array, B from int8 bank image.
// 10 A-words (Hankel-shared) + 16 B-words per kc -> 32 IMMAs per kc.
#define IMLOOP(APTR, BPTR)                                                     \
    {                                                                          \
        const uint32_t* _ap = (APTR);                                          \
        const uint32_t* _bp = (BPTR);                                          \
        _Pragma("unroll")                                                      \
        for (int kc = 0; kc < 8; kc++) {                                       \
            uint32_t w10[10];                                                  \
            _Pragma("unroll")                                                  \
            for (int u = 0; u < 10; u++) w10[u] = _ap[kc * 8 + 2 * u];         \
            _Pragma("unroll")                                                  \
            for (int gq = 0; gq < 8; gq++) {                                   \
                uint32_t b0 = _bp[gq * 8 * 68 + kc * 8];                       \
                uint32_t b1 = _bp[gq * 8 * 68 + kc * 8 + 4];                   \
                _Pragma("unroll")                                              \
                for (int ms = 0; ms < 4; ms++)                                 \
                    imma(d + (ms * 8 + gq) * 4,                                \
                         w10[2 * ms], w10[2 * ms + 1],                         \
                         w10[2 * ms + 2], w10[2 * ms + 3], b0, b1);            \
            }                                                                  \
        }                                                                      \
    }

__global__ void __launch_bounds__(NTHREADS, 1)
conv_kernel(const float* __restrict__ x, float* __restrict__ out) {
    extern __shared__ unsigned char smem[];
    float* xw = (float*)(smem + XW_OFF);
    uint32_t* H0w = (uint32_t*)(smem + H0_OFF);
    uint32_t* L0w = (uint32_t*)(smem + L0_OFF);
    uint32_t* XHS = (uint32_t*)(smem + XHS_OFF);
    uint32_t* XLS = (uint32_t*)(smem + XLS_OFF);
    float* fsc  = (float*)(smem + FS_OFF);
    float* wmx  = (float*)(smem + WM_OFF);
    unsigned int* sgp = (unsigned int*)(smem + SG_OFF);

    int tid  = threadIdx.x;
    int wid  = tid >> 5;
    int lane = tid & 31;
    int lq   = lane >> 2;     // groupID 0..7
    int lr   = lane & 3;      // tig 0..3
    int ss   = lq & 3;        // byte-stagger class
    int aoff = wid * 16 + (lq >> 2) + lr;    // A word offset within stagger array
    const uint32_t* aph = XHS + ss * 200 + aoff;
    const uint32_t* apl = XLS + ss * 200 + aoff;
    const uint32_t* bph = (const uint32_t*)(smem + B8H_OFF) + lq * 68 + lr;
    const uint32_t* bpl = (const uint32_t*)(smem + B8L_OFF) + lq * 68 + lr;

    if (tid == 0) sgp[0] = atomicAdd(&g_counter, 1u);
    __syncthreads();
    unsigned int g = sgp[0];

    // prefetch first tile's window: xw[j] = x[b, t0-128+j, c], j in [0,768)
    float v0 = 0, v1 = 0, v2 = 0;
    {
        unsigned int gc = (g < NTILES) ? g : 0u;
        int c2 = gc >> 9, b2 = (gc >> 5) & 15, t02 = (int)(gc & 31) << 9;
        const float* xb = x + (size_t)b2 * LL * CC + c2;
        int l = t02 - 128 + tid;
        v0 = (l >= 0 && l < LL) ? xb[(size_t)l * CC] : 0.0f;
        v1 = (l + 256 < LL) ? xb[(size_t)(l + 256) * CC] : 0.0f;
        v2 = (l + 512 < LL) ? xb[(size_t)(l + 512) * CC] : 0.0f;
    }

    int cur_c = -1;
    while (g < NTILES) {
        int c = g >> 9, b = (g >> 5) & 15, t0 = (int)(g & 31) << 9;

        __syncthreads();   // B1: previous tile's smem readers done

        if (c != cur_c) {  // stage int8 bank + scales for this channel
            const uint4* sH = (const uint4*)g_b8h[c];
            const uint4* sL = (const uint4*)g_b8l[c];
            uint4* dH = (uint4*)(smem + B8H_OFF);
            uint4* dL = (uint4*)(smem + B8L_OFF);
            for (int i = tid; i < 1088; i += NTHREADS) { dH[i] = sH[i]; dL[i] = sL[i]; }
            if (tid < 64) fsc[tid] = g_fs[c][tid];
            cur_c = c;
        }

        // stage fp32 window + per-warp |x| max
        xw[tid] = v0; xw[tid + 256] = v1; xw[tid + 512] = v2;
        {
            float am = fmaxf(fabsf(v0), fmaxf(fabsf(v1), fabsf(v2)));
#pragma unroll
            for (int o = 16; o; o >>= 1) am = fmaxf(am, __shfl_xor_sync(~0u, am, o));
            if (lane == 0) wmx[wid] = am;
        }
        if (tid == 0) sgp[0] = atomicAdd(&g_counter, 1u);
        __syncthreads();   // B2
        unsigned int gn = sgp[0];

        // uniform tile scale
        float maxv = wmx[0];
#pragma unroll
        for (int i = 1; i < 8; i++) maxv = fmaxf(maxv, wmx[i]);
        maxv = fmaxf(maxv, 1e-20f);
        float inv = 127.0f / maxv;
        float sq  = maxv * (1.0f / 127.0f);

        // prefetch next tile (hidden under build + MMA)
        {
            unsigned int gc = (gn < NTILES) ? gn : 0u;
            int c2 = gc >> 9, b2 = (gc >> 5) & 15, t02 = (int)(gc & 31) << 9;
            const float* xb = x + (size_t)b2 * LL * CC + c2;
            int l = t02 - 128 + tid;
            v0 = (l >= 0 && l < LL) ? xb[(size_t)l * CC] : 0.0f;
            v1 = (l + 256 < LL) ? xb[(size_t)(l + 256) * CC] : 0.0f;
            v2 = (l + 512 < LL) ? xb[(size_t)(l + 512) * CC] : 0.0f;
        }

        // quantize: 4 x-values/thread -> packed int8 hi/lo words
        if (tid < 192) {
            float4 xv = *(const float4*)(xw + 4 * tid);
            uint32_t hw = 0, lw = 0;
            const float* xe = (const float*)&xv;
#pragma unroll
            for (int e = 0; e < 3 + 1; e++) {
                float fq = xe[e] * inv;
                int h = __float2int_rn(fq);
                int l8 = __float2int_rn((fq - (float)h) * 256.0f);
                l8 = max(-127, min(127, l8));
                hw |= ((uint32_t)h & 255u) << (8 * e);
                lw |= ((uint32_t)l8 & 255u) << (8 * e);
            }
            H0w[tid] = hw; L0w[tid] = lw;
        } else if (tid == 192) {
            H0w[192] = 0; L0w[192] = 0;
        }
        __syncthreads();   // B3

        // byte-staggered copies (s = 0..3)
        if (tid < 192) {
            uint32_t a0 = H0w[tid], a1 = H0w[tid + 1];
            XHS[tid]       = a0;
            XHS[200 + tid] = __byte_perm(a0, a1, 0x4321);
            XHS[400 + tid] = __byte_perm(a0, a1, 0x5432);
            XHS[600 + tid] = __byte_perm(a0, a1, 0x6543);
            uint32_t c0 = L0w[tid], c1 = L0w[tid + 1];
            XLS[tid]       = c0;
            XLS[200 + tid] = __byte_perm(c0, c1, 0x4321);
            XLS[400 + tid] = __byte_perm(c0, c1, 0x5432);
            XLS[600 + tid] = __byte_perm(c0, c1, 0x6543);
        }
        __syncthreads();   // B4

        // ---- int8 GEMM: hL + lH, rescale >>8, then hH on top ----
        int d[128];
#pragma unroll
        for (int i = 0; i < 128; i++) d[i] = 0;

        IMLOOP(aph, bpl);          // h * L
        IMLOOP(apl, bph);          // l * H
#pragma unroll
        for (int i = 0; i < 128; i++) d[i] = (d[i] + 128) >> 8;
        IMLOOP(aph, bph);          // h * H

        // ---- epilogue: rescale, power, store ----
        size_t ob = ((size_t)(b * LL + t0 + wid * 64 + lq)) * (CC * RR)
                  + (size_t)c * RR;
#pragma unroll
        for (int gq = 0; gq < 8; gq++) {
            int rr = gq * 4 + lr;
            float pr = sq * fsc[2 * rr];
            float pi = sq * fsc[2 * rr + 1];
#pragma unroll
            for (int ms = 0; ms < 4; ms++) {
                const int* dd = d + (ms * 8 + gq) * 4;
                float c0 = (float)dd[0] * pr;
                float c1 = (float)dd[1] * pi;
                float c2 = (float)dd[2] * pr;
                float c3 = (float)dd[3] * pi;
                float p0 = c0 * c0 + c1 * c1;
                float p1 = c2 * c2 + c3 * c3;
                out[ob + (size_t)(ms * 16) * (CC * RR) + rr] = p0;
                out[ob + (size_t)(ms * 16 + 8) * (CC * RR) + rr] = p1;
            }
        }

        g = gn;
    }
}

extern "C" void kernel_launch(void* const* d_in, const int* in_sizes, int n_in,
                              void* d_out, int out_size) {
    const float* x  = (const float*)d_in[0];
    const float* kV = (const float*)d_in[1];
    const float* sV = (const float*)d_in[2];
    float* out = (float*)d_out;

    cudaFuncSetAttribute(conv_kernel, cudaFuncAttributeMaxDynamicSharedMemorySize,
                         SMEM_BYTES);

    // 1) int8 Gabor bank + per-column scales + queue reset
    bank_kernel<<<256, 256>>>(kV, sV);

    // 2) persistent implicit-GEMM wavelet transform (IMMA s8, K=32/instr)
    conv_kernel<<<NBLOCKS, NTHREADS, SMEM_BYTES>>>(x, out);
}

// round 10
// speedup vs baseline: 2.7695x; 2.7695x over previous
#include <cuda_runtime.h>
#include <cuda_bf16.h>
#include <math.h>
#include <stdint.h>

// Problem constants
#define BB 16
#define CC 8
#define LL 16384
#define RR 32

#define TM 512                 // t rows per CTA tile
#define NTILES 4096            // c-major: c=g>>9, b=(g>>5)&15, seg=g&31
#define NBLOCKS 152
#define NTHREADS 256           // 8 warps, each warp: m64 x n64

#define BSTRIDE 132            // uint32 words per B row (264 bf16, padded)

// SMEM offsets (bytes)
#define BH_OFF 0                         // B_hi: 64 rows * 132 words = 33792 B
#define BL_OFF 33792                     // B_lo
#define XW_OFF 67584                     // fp32 window: 776 floats
#define PEH_OFF (XW_OFF + 3104)          // even-pair hi: 384 words (+16 pad)
#define POH_OFF (PEH_OFF + 1600)
#define PEL_OFF (POH_OFF + 1600)
#define POL_OFF (PEL_OFF + 1600)
#define SG_OFF  (POL_OFF + 1600)
#define SMEM_BYTES (SG_OFF + 16)

// Gabor bank, bf16 hi/lo, padded: row n (0..63) = 2*pos + (0=re,1=im), tap w
__device__ __align__(16) __nv_bfloat16 g_bh[CC][64 * 2 * BSTRIDE];
__device__ __align__(16) __nv_bfloat16 g_bl[CC][64 * 2 * BSTRIDE];
__device__ int   g_pr[CC][32];   // sorted pos -> actual output r
// Level tables: .x/.y = center-out kc order (16 nibbles);
//               .z/.w = cum[1..4], cum[5..8] (bytes), cum[l] = #kc with ng>=l
__device__ uint4 g_tab[CC];
__device__ unsigned int g_counter;

__global__ void bank_kernel(const float* __restrict__ kV, const float* __restrict__ sV) {
    int idx = blockIdx.x * blockDim.x + threadIdx.x;
    if (idx == 0) g_counter = 0;
    if (idx >= 65536) return;
    int f = idx >> 8, w = idx & 255;
    int c = f >> 5, j = f & 31;
    float k = kV[f], s = sV[f];

    // sort rank within channel, sigma DESC (pos 0 = largest sigma), tie by j
    int pos = 0;
    for (int j2 = 0; j2 < 32; j2++) {
        float s2 = sV[c * 32 + j2];
        pos += (s2 > s) || (s2 == s && j2 < j);
    }

    float phase = ((float)(-2.0 * M_PI / 256.0) * k) * (float)w;
    double sp, cp;
    sincos((double)phase, &sp, &cp);
    float nm = (float)w - 128.0f;
    float s2v = s * s;
    float inv2s2 = 1.0f / (2.0f * s2v);
    float coef = 1.0f / sqrtf(2.0f * (float)M_PI * s2v);
    float gauss = coef * expf(-inv2s2 * nm * nm);
    float fre = (float)cp * gauss, fim = (float)sp * gauss;

    __nv_bfloat16 h = __float2bfloat16(fre);
    __nv_bfloat16 l = __float2bfloat16(fre - __bfloat162float(h));
    g_bh[c][(2 * pos) * 264 + w] = h;
    g_bl[c][(2 * pos) * 264 + w] = l;
    h = __float2bfloat16(fim);
    l = __float2bfloat16(fim - __bfloat162float(h));
    g_bh[c][(2 * pos + 1) * 264 + w] = h;
    g_bl[c][(2 * pos + 1) * 264 + w] = l;

    if (w == 0) g_pr[c][pos] = 31 - j;   // reference reverses R

    if (w == 0 && j == 0) {  // one thread per channel: level tables
        // per-group support interval (group = 4 sorted positions; max sigma
        // = sorted position 4*gq since sort is descending)
        int kl[8], kh[8];
        for (int gq = 0; gq < 8; gq++) {
            float sg = 4.0f;
            for (int j2 = 0; j2 < 32; j2++) {
                float sj2 = sV[c * 32 + j2];
                int p2 = 0;
                for (int j3 = 0; j3 < 32; j3++) {
                    float sj3 = sV[c * 32 + j3];
                    p2 += (sj3 > sj2) || (sj3 == sj2 && j3 < j2);
                }
                if (p2 == 4 * gq) sg = sj2;
            }
            float D = 4.5f * sg;
            int a = (int)floorf((128.0f - D) * (1.0f / 16.0f));
            int e = (int)floorf((128.0f + D) * (1.0f / 16.0f));
            kl[gq] = a < 0 ? 0 : a;
            kh[gq] = e > 15 ? 15 : e;
        }
        int ng[16];
        for (int kc = 0; kc < 16; kc++) {
            int cnt = 0;
            for (int gq = 0; gq < 8; gq++) cnt += (kl[gq] <= kc && kc <= kh[gq]);
            ng[kc] = cnt;
        }
        // counting sort kc by ng descending -> ord nibbles + cum bytes
        unsigned long long ord = 0ull;
        int cum[10];
        int ip = 0;
        for (int l2 = 8; l2 >= 1; l2--) {
            for (int kc = 0; kc < 16; kc++) {
                if (ng[kc] == l2) {
                    ord |= (unsigned long long)kc << (4 * ip);
                    ip++;
                }
            }
            cum[l2] = ip;
        }
        uint4 tab;
        tab.x = (unsigned int)(ord & 0xFFFFFFFFull);
        tab.y = (unsigned int)(ord >> 32);
        tab.z = (unsigned int)cum[1] | ((unsigned int)cum[2] << 8) |
                ((unsigned int)cum[3] << 16) | ((unsigned int)cum[4] << 24);
        tab.w = (unsigned int)cum[5] | ((unsigned int)cum[6] << 8) |
                ((unsigned int)cum[7] << 16) | ((unsigned int)cum[8] << 24);
        g_tab[c] = tab;
    }
}

__device__ __forceinline__ uint32_t pack2(__nv_bfloat16 a, __nv_bfloat16 b) {
    __nv_bfloat162 t(a, b);
    return *reinterpret_cast<uint32_t*>(&t);
}

__device__ __forceinline__ void mma16816(float* d,
                                         uint32_t a0, uint32_t a1, uint32_t a2, uint32_t a3,
                                         uint32_t b0, uint32_t b1) {
    asm volatile(
        "mma.sync.aligned.m16n8k16.row.col.f32.bf16.bf16.f32 "
        "{%0,%1,%2,%3}, {%4,%5,%6,%7}, {%8,%9}, {%0,%1,%2,%3};"
        : "+f"(d[0]), "+f"(d[1]), "+f"(d[2]), "+f"(d[3])
        : "r"(a0), "r"(a1), "r"(a2), "r"(a3), "r"(b0), "r"(b1));
}

__global__ void __launch_bounds__(NTHREADS, 1)
conv_kernel(const float* __restrict__ x, float* __restrict__ out) {
    extern __shared__ unsigned char smem[];
    float* xw = (float*)(smem + XW_OFF);
    uint32_t* PEHw = (uint32_t*)(smem + PEH_OFF);
    uint32_t* POHw = (uint32_t*)(smem + POH_OFF);
    uint32_t* PELw = (uint32_t*)(smem + PEL_OFF);
    uint32_t* POLw = (uint32_t*)(smem + POL_OFF);
    const uint32_t* BHw = (const uint32_t*)(smem + BH_OFF);
    const uint32_t* BLw = (const uint32_t*)(smem + BL_OFF);
    unsigned int* sgp = (unsigned int*)(smem + SG_OFF);

    int tid  = threadIdx.x;
    int wid  = tid >> 5;
    int lane = tid & 31;
    int lq   = lane >> 2;     // 0..7
    int lr   = lane & 3;      // 0..3
    int mwarp = wid * 64;
    int odd = lq & 1;
    int abase = (mwarp >> 1) + (lq >> 1) + lr;

    if (tid == 0) sgp[0] = atomicAdd(&g_counter, 1u);
    __syncthreads();
    unsigned int g = sgp[0];

    // prefetch first tile's x window: xw[j] = x[b, t0-128+j, c], j in [0,769)
    float v0 = 0, v1 = 0, v2 = 0, v3 = 0;
    {
        unsigned int gc = (g < NTILES) ? g : 0u;
        int c2 = gc >> 9, b2 = (gc >> 5) & 15, t02 = (int)(gc & 31) << 9;
        const float* xb = x + (size_t)b2 * LL * CC + c2;
        int l = t02 - 128 + tid;
        v0 = (l >= 0 && l < LL) ? xb[(size_t)l * CC] : 0.0f;
        v1 = (l + 256 < LL) ? xb[(size_t)(l + 256) * CC] : 0.0f;
        v2 = (l + 512 < LL) ? xb[(size_t)(l + 512) * CC] : 0.0f;
        if (tid == 0) { int l3 = t02 + 640; v3 = (l3 < LL) ? xb[(size_t)l3 * CC] : 0.0f; }
    }

    int cur_c = -1;
    unsigned long long ordv = 0ull;
    int cums[10];
    cums[9] = 0;
    int rcol[8];
    while (g < NTILES) {
        int c = g >> 9, b = (g >> 5) & 15, t0 = (int)(g & 31) << 9;

        __syncthreads();   // B1: previous tile's smem readers done

        if (c != cur_c) {  // stage B + per-channel tables
            const uint4* sH = (const uint4*)g_bh[c];
            const uint4* sL = (const uint4*)g_bl[c];
            uint4* dH = (uint4*)(smem + BH_OFF);
            uint4* dL = (uint4*)(smem + BL_OFF);
            for (int i = tid; i < 2112; i += NTHREADS) { dH[i] = sH[i]; dL[i] = sL[i]; }
            uint4 tab = g_tab[c];
            ordv = (unsigned long long)tab.x | ((unsigned long long)tab.y << 32);
#pragma unroll
            for (int l2 = 1; l2 <= 4; l2++) cums[l2] = (int)((tab.z >> ((l2 - 1) * 8)) & 255u);
#pragma unroll
            for (int l2 = 5; l2 <= 8; l2++) cums[l2] = (int)((tab.w >> ((l2 - 5) * 8)) & 255u);
#pragma unroll
            for (int ns = 0; ns < 8; ns++) rcol[ns] = c * RR + g_pr[c][ns * 4 + lr];
            cur_c = c;
        }

        // stage fp32 window
        xw[tid] = v0; xw[tid + 256] = v1; xw[tid + 512] = v2;
        if (tid == 0) xw[768] = v3;
        if (tid == 0) sgp[1] = atomicAdd(&g_counter, 1u);
        __syncthreads();   // mid: xw visible

        // build hi/lo even/odd bf16-pair arrays (384 entries)
        {
            int i = tid;
            {
                float a0 = xw[2 * i], a1 = xw[2 * i + 1], a2 = xw[2 * i + 2];
                __nv_bfloat16 h0 = __float2bfloat16(a0);
                __nv_bfloat16 l0 = __float2bfloat16(a0 - __bfloat162float(h0));
                __nv_bfloat16 h1 = __float2bfloat16(a1);
                __nv_bfloat16 l1 = __float2bfloat16(a1 - __bfloat162float(h1));
                __nv_bfloat16 h2 = __float2bfloat16(a2);
                __nv_bfloat16 l2 = __float2bfloat16(a2 - __bfloat162float(h2));
                PEHw[i] = pack2(h0, h1); POHw[i] = pack2(h1, h2);
                PELw[i] = pack2(l0, l1); POLw[i] = pack2(l1, l2);
            }
            if (tid < 128) {
                i = tid + 256;
                float a0 = xw[2 * i], a1 = xw[2 * i + 1], a2 = xw[2 * i + 2];
                __nv_bfloat16 h0 = __float2bfloat16(a0);
                __nv_bfloat16 l0 = __float2bfloat16(a0 - __bfloat162float(h0));
                __nv_bfloat16 h1 = __float2bfloat16(a1);
                __nv_bfloat16 l1 = __float2bfloat16(a1 - __bfloat162float(h1));
                __nv_bfloat16 h2 = __float2bfloat16(a2);
                __nv_bfloat16 l2 = __float2bfloat16(a2 - __bfloat162float(h2));
                PEHw[i] = pack2(h0, h1); POHw[i] = pack2(h1, h2);
                PELw[i] = pack2(l0, l1); POLw[i] = pack2(l1, l2);
            }
        }
        __syncthreads();   // B2
        unsigned int gn = sgp[1];

        // prefetch next tile's x (hidden under the MMA mainloop)
        {
            unsigned int gc = (gn < NTILES) ? gn : 0u;
            int c2 = gc >> 9, b2 = (gc >> 5) & 15, t02 = (int)(gc & 31) << 9;
            const float* xb = x + (size_t)b2 * LL * CC + c2;
            int l = t02 - 128 + tid;
            v0 = (l >= 0 && l < LL) ? xb[(size_t)l * CC] : 0.0f;
            v1 = (l + 256 < LL) ? xb[(size_t)(l + 256) * CC] : 0.0f;
            v2 = (l + 512 < LL) ? xb[(size_t)(l + 512) * CC] : 0.0f;
            if (tid == 0) { int l3 = t02 + 640; v3 = (l3 < LL) ? xb[(size_t)l3 * CC] : 0.0f; }
        }

        // ---- 3-pass hi/lo bf16 GEMM, sigma truncation via level blocks ----
        // Level block l: runtime loop over center-out-ordered kc's with
        // exactly-l active n-groups; body is dense (A loaded once, l groups,
        // all accumulator indices compile-time). No predication anywhere.
        float d[128];
#pragma unroll
        for (int i = 0; i < 128; i++) d[i] = 0.0f;

#pragma unroll 1
        for (int pass = 0; pass < 3; pass++) {
            const uint32_t* ap = (pass == 2) ? (odd ? POLw : PELw)
                                             : (odd ? POHw : PEHw);
            const uint32_t* bl = ((pass == 1) ? BLw : BHw) + lq * BSTRIDE + lr;
            const uint32_t* aw = ap + abase;
#pragma unroll
            for (int lv = 8; lv >= 1; lv--) {
                int i1 = cums[lv];
#pragma unroll 1
                for (int idx = cums[lv + 1]; idx < i1; idx++) {
                    int kc = (int)((ordv >> (4 * idx)) & 15ull);
                    const uint32_t* ak = aw + kc * 8;
                    uint32_t w9[9];
#pragma unroll
                    for (int u = 0; u < 9; u++) w9[u] = ak[4 * u];
                    const uint32_t* bk = bl + kc * 8;
#pragma unroll
                    for (int gq = 0; gq < lv; gq++) {
                        uint32_t b0 = bk[gq * 8 * BSTRIDE];
                        uint32_t b1 = bk[gq * 8 * BSTRIDE + 4];
#pragma unroll
                        for (int ms = 0; ms < 4; ms++)
                            mma16816(d + (ms * 8 + gq) * 4,
                                     w9[2 * ms], w9[2 * ms + 1],
                                     w9[2 * ms + 1], w9[2 * ms + 2], b0, b1);
                    }
                }
            }
        }

        // ---- epilogue: power + permuted store ----
        size_t ob = ((size_t)(b * LL + t0 + mwarp + lq)) * (CC * RR);
#pragma unroll
        for (int ms = 0; ms < 4; ms++) {
#pragma unroll
            for (int ns = 0; ns < 8; ns++) {
                const float* dd = d + (ms * 8 + ns) * 4;
                float p0 = dd[0] * dd[0] + dd[1] * dd[1];
                float p1 = dd[2] * dd[2] + dd[3] * dd[3];
                out[ob + (size_t)(ms * 16) * (CC * RR) + rcol[ns]] = p0;
                out[ob + (size_t)(ms * 16 + 8) * (CC * RR) + rcol[ns]] = p1;
            }
        }

        g = gn;
    }
}

extern "C" void kernel_launch(void* const* d_in, const int* in_sizes, int n_in,
                              void* d_out, int out_size) {
    const float* x  = (const float*)d_in[0];
    const float* kV = (const float*)d_in[1];
    const float* sV = (const float*)d_in[2];
    float* out = (float*)d_out;

    cudaFuncSetAttribute(conv_kernel, cudaFuncAttributeMaxDynamicSharedMemorySize,
                         SMEM_BYTES);

    // 1) Gabor bank (sigma-sorted, bf16 hi/lo) + level tables + queue reset
    bank_kernel<<<256, 256>>>(kV, sV);

    // 2) persistent implicit-GEMM wavelet transform (level-loop truncation)
    conv_kernel<<<NBLOCKS, NTHREADS, SMEM_BYTES>>>(x, out);
}

// round 11
// speedup vs baseline: 3.1451x; 1.1356x over previous
#include <cuda_runtime.h>
#include <cuda_bf16.h>
#include <math.h>
#include <stdint.h>

// Problem constants
#define BB 16
#define CC 8
#define LL 16384
#define RR 32

#define TM 256                 // t rows per CTA tile
#define NTILES 8192            // c-major: c=g>>10, b=(g>>6)&15, seg=g&63
#define NBLOCKS 304            // 2 CTAs per SM
#define NTHREADS 256           // 8 warps; warp = m64 x n32 (one n-half)

#define BSTRIDE 132            // uint32 words per B row (264 bf16, padded)

// SMEM offsets (bytes)
#define BH_OFF 0                         // B_hi: 64 rows * 132 words = 33792 B
#define BL_OFF 33792                     // B_lo
#define XW_OFF 67584                     // fp32 window: 544 floats (2176 B)
#define PEH_OFF (XW_OFF + 2176)          // even-pair hi: 272 words (1152B stride)
#define POH_OFF (PEH_OFF + 1152)
#define PEL_OFF (POH_OFF + 1152)
#define POL_OFF (PEL_OFF + 1152)
#define SG_OFF  (POL_OFF + 1152)
#define SMEM_BYTES (SG_OFF + 16)         // 74384 B -> 2 CTAs fit in 228KB

// Gabor bank, bf16 hi/lo, padded: row n (0..63) = 2*pos + (0=re,1=im), tap w
__device__ __align__(16) __nv_bfloat16 g_bh[CC][64 * 2 * BSTRIDE];
__device__ __align__(16) __nv_bfloat16 g_bl[CC][64 * 2 * BSTRIDE];
__device__ int   g_pr[CC][32];      // sorted pos -> actual output r
// Per-half level tables: [c][h]: .x/.y = kc order nibbles (by in-half count
// desc), .z = cum[1..4] bytes (cum[l] = #kc with count >= l), .w unused
__device__ uint4 g_tab[CC][2];
__device__ unsigned int g_counter;

__global__ void bank_kernel(const float* __restrict__ kV, const float* __restrict__ sV) {
    int idx = blockIdx.x * blockDim.x + threadIdx.x;
    if (idx == 0) g_counter = 0;
    if (idx >= 65536) return;
    int f = idx >> 8, w = idx & 255;
    int c = f >> 5, j = f & 31;
    float k = kV[f], s = sV[f];

    // sort rank within channel, sigma DESC (pos 0 = largest sigma), tie by j
    int pos = 0;
    for (int j2 = 0; j2 < 32; j2++) {
        float s2 = sV[c * 32 + j2];
        pos += (s2 > s) || (s2 == s && j2 < j);
    }

    float phase = ((float)(-2.0 * M_PI / 256.0) * k) * (float)w;
    double sp, cp;
    sincos((double)phase, &sp, &cp);
    float nm = (float)w - 128.0f;
    float s2v = s * s;
    float inv2s2 = 1.0f / (2.0f * s2v);
    float coef = 1.0f / sqrtf(2.0f * (float)M_PI * s2v);
    float gauss = coef * expf(-inv2s2 * nm * nm);
    float fre = (float)cp * gauss, fim = (float)sp * gauss;

    __nv_bfloat16 h = __float2bfloat16(fre);
    __nv_bfloat16 l = __float2bfloat16(fre - __bfloat162float(h));
    g_bh[c][(2 * pos) * 264 + w] = h;
    g_bl[c][(2 * pos) * 264 + w] = l;
    h = __float2bfloat16(fim);
    l = __float2bfloat16(fim - __bfloat162float(h));
    g_bh[c][(2 * pos + 1) * 264 + w] = h;
    g_bl[c][(2 * pos + 1) * 264 + w] = l;

    if (w == 0) g_pr[c][pos] = 31 - j;   // reference reverses R

    if (w == 0 && j == 0) {  // one thread per channel: per-half level tables
        int kl[8], kh[8];
        for (int gq = 0; gq < 8; gq++) {
            float sg = 4.0f;
            for (int j2 = 0; j2 < 32; j2++) {
                float sj2 = sV[c * 32 + j2];
                int p2 = 0;
                for (int j3 = 0; j3 < 32; j3++) {
                    float sj3 = sV[c * 32 + j3];
                    p2 += (sj3 > sj2) || (sj3 == sj2 && j3 < j2);
                }
                if (p2 == 4 * gq) sg = sj2;
            }
            float D = 4.5f * sg;
            int a = (int)floorf((128.0f - D) * (1.0f / 16.0f));
            int e = (int)floorf((128.0f + D) * (1.0f / 16.0f));
            kl[gq] = a < 0 ? 0 : a;
            kh[gq] = e > 15 ? 15 : e;
        }
        for (int hh = 0; hh < 2; hh++) {
            int cnt[16];
            for (int kc = 0; kc < 16; kc++) {
                int cn = 0;
                for (int gq = 4 * hh; gq < 4 * hh + 4; gq++)
                    cn += (kl[gq] <= kc && kc <= kh[gq]);
                cnt[kc] = cn;
            }
            unsigned long long ord = 0ull;
            int cum[6];
            int ip = 0;
            for (int l2 = 4; l2 >= 1; l2--) {
                for (int kc = 0; kc < 16; kc++)
                    if (cnt[kc] == l2) {
                        ord |= (unsigned long long)kc << (4 * ip);
                        ip++;
                    }
                cum[l2] = ip;
            }
            uint4 tab;
            tab.x = (unsigned int)(ord & 0xFFFFFFFFull);
            tab.y = (unsigned int)(ord >> 32);
            tab.z = (unsigned int)cum[1] | ((unsigned int)cum[2] << 8) |
                    ((unsigned int)cum[3] << 16) | ((unsigned int)cum[4] << 24);
            tab.w = 0;
            g_tab[c][hh] = tab;
        }
    }
}

__device__ __forceinline__ uint32_t pack2(__nv_bfloat16 a, __nv_bfloat16 b) {
    __nv_bfloat162 t(a, b);
    return *reinterpret_cast<uint32_t*>(&t);
}

__device__ __forceinline__ void mma16816(float* d,
                                         uint32_t a0, uint32_t a1, uint32_t a2, uint32_t a3,
                                         uint32_t b0, uint32_t b1) {
    asm volatile(
        "mma.sync.aligned.m16n8k16.row.col.f32.bf16.bf16.f32 "
        "{%0,%1,%2,%3}, {%4,%5,%6,%7}, {%8,%9}, {%0,%1,%2,%3};"
        : "+f"(d[0]), "+f"(d[1]), "+f"(d[2]), "+f"(d[3])
        : "r"(a0), "r"(a1), "r"(a2), "r"(a3), "r"(b0), "r"(b1));
}

__global__ void __launch_bounds__(NTHREADS, 2)
conv_kernel(const float* __restrict__ x, float* __restrict__ out) {
    extern __shared__ unsigned char smem[];
    float* xw = (float*)(smem + XW_OFF);
    uint32_t* PEHw = (uint32_t*)(smem + PEH_OFF);
    uint32_t* POHw = (uint32_t*)(smem + POH_OFF);
    uint32_t* PELw = (uint32_t*)(smem + PEL_OFF);
    uint32_t* POLw = (uint32_t*)(smem + POL_OFF);
    const uint32_t* BHw = (const uint32_t*)(smem + BH_OFF);
    const uint32_t* BLw = (const uint32_t*)(smem + BL_OFF);
    unsigned int* sgp = (unsigned int*)(smem + SG_OFF);

    int tid  = threadIdx.x;
    int wid  = tid >> 5;
    int lane = tid & 31;
    int lq   = lane >> 2;     // 0..7
    int lr   = lane & 3;      // 0..3
    int half = wid & 1;       // n-half: groups 4*half .. 4*half+3
    int mwarp = (wid >> 1) * 64;
    int odd = lq & 1;
    int abase = (mwarp >> 1) + (lq >> 1) + lr;

    if (tid == 0) sgp[0] = atomicAdd(&g_counter, 1u);
    __syncthreads();
    unsigned int g = sgp[0];

    // prefetch first tile's x window: xw[j] = x[b, t0-128+j, c], j in [0,544)
    float v0 = 0, v1 = 0;
    {
        unsigned int gc = (g < NTILES) ? g : 0u;
        int c2 = gc >> 10, b2 = (gc >> 6) & 15, t02 = (int)(gc & 63) << 8;
        const float* xb = x + (size_t)b2 * LL * CC + c2;
        int l = t02 - 128 + tid;
        v0 = (l >= 0 && l < LL) ? xb[(size_t)l * CC] : 0.0f;
        if (tid < 288) {
            int l1 = l + 256;
            v1 = (l1 >= 0 && l1 < LL) ? xb[(size_t)l1 * CC] : 0.0f;
        }
    }

    int cur_c = -1;
    unsigned long long ordv = 0ull;
    int cum1 = 0, cum2 = 0, cum3 = 0, cum4 = 0;
    int rcol[4];
    while (g < NTILES) {
        int c = g >> 10, b = (g >> 6) & 15, t0 = (int)(g & 63) << 8;

        __syncthreads();   // B1: previous tile's smem readers done

        if (c != cur_c) {  // stage B + per-channel tables
            const uint4* sH = (const uint4*)g_bh[c];
            const uint4* sL = (const uint4*)g_bl[c];
            uint4* dH = (uint4*)(smem + BH_OFF);
            uint4* dL = (uint4*)(smem + BL_OFF);
            for (int i = tid; i < 2112; i += NTHREADS) { dH[i] = sH[i]; dL[i] = sL[i]; }
            uint4 tab = g_tab[c][half];
            ordv = (unsigned long long)tab.x | ((unsigned long long)tab.y << 32);
            cum1 = (int)(tab.z & 255u);
            cum2 = (int)((tab.z >> 8) & 255u);
            cum3 = (int)((tab.z >> 16) & 255u);
            cum4 = (int)((tab.z >> 24) & 255u);
#pragma unroll
            for (int gq = 0; gq < 4; gq++)
                rcol[gq] = c * RR + g_pr[c][(4 * half + gq) * 4 + lr];
            cur_c = c;
        }

        // stage fp32 window
        xw[tid] = v0;
        if (tid < 288) xw[256 + tid] = v1;
        if (tid == 0) sgp[1] = atomicAdd(&g_counter, 1u);
        __syncthreads();   // mid: xw visible

        // build hi/lo even/odd bf16-pair arrays (264 entries)
        if (tid < 264) {
            float a0 = xw[2 * tid], a1 = xw[2 * tid + 1], a2 = xw[2 * tid + 2];
            __nv_bfloat16 h0 = __float2bfloat16(a0);
            __nv_bfloat16 l0 = __float2bfloat16(a0 - __bfloat162float(h0));
            __nv_bfloat16 h1 = __float2bfloat16(a1);
            __nv_bfloat16 l1 = __float2bfloat16(a1 - __bfloat162float(h1));
            __nv_bfloat16 h2 = __float2bfloat16(a2);
            __nv_bfloat16 l2 = __float2bfloat16(a2 - __bfloat162float(h2));
            PEHw[tid] = pack2(h0, h1); POHw[tid] = pack2(h1, h2);
            PELw[tid] = pack2(l0, l1); POLw[tid] = pack2(l1, l2);
        }
        __syncthreads();   // B2
        unsigned int gn = sgp[1];

        // prefetch next tile's x (hidden under the MMA mainloop)
        {
            unsigned int gc = (gn < NTILES) ? gn : 0u;
            int c2 = gc >> 10, b2 = (gc >> 6) & 15, t02 = (int)(gc & 63) << 8;
            const float* xb = x + (size_t)b2 * LL * CC + c2;
            int l = t02 - 128 + tid;
            v0 = (l >= 0 && l < LL) ? xb[(size_t)l * CC] : 0.0f;
            if (tid < 288) {
                int l1 = l + 256;
                v1 = (l1 >= 0 && l1 < LL) ? xb[(size_t)l1 * CC] : 0.0f;
            }
        }

        // ---- 3-pass hi/lo bf16 GEMM, per-half level-loop truncation ----
        // Level block lv: kc's where exactly lv of this warp's 4 n-groups are
        // active (nested: active groups = first lv). A loaded once per kc.
        float d[64];
#pragma unroll
        for (int i = 0; i < 64; i++) d[i] = 0.0f;

#pragma unroll 1
        for (int pass = 0; pass < 3; pass++) {
            const uint32_t* ap = (pass == 2) ? (odd ? POLw : PELw)
                                             : (odd ? POHw : PEHw);
            const uint32_t* bl = ((pass == 1) ? BLw : BHw)
                               + (4 * half) * 8 * BSTRIDE + lq * BSTRIDE + lr;
            const uint32_t* aw = ap + abase;
#pragma unroll
            for (int lv = 4; lv >= 1; lv--) {
                int i0 = (lv == 4) ? 0 : ((lv == 3) ? cum4 : ((lv == 2) ? cum3 : cum2));
                int i1 = (lv == 4) ? cum4 : ((lv == 3) ? cum3 : ((lv == 2) ? cum2 : cum1));
#pragma unroll 1
                for (int idx = i0; idx < i1; idx++) {
                    int kc = (int)((ordv >> (4 * idx)) & 15ull);
                    const uint32_t* ak = aw + kc * 8;
                    uint32_t w9[9];
#pragma unroll
                    for (int u = 0; u < 9; u++) w9[u] = ak[4 * u];
                    const uint32_t* bk = bl + kc * 8;
#pragma unroll
                    for (int gq = 0; gq < lv; gq++) {
                        uint32_t b0 = bk[gq * 8 * BSTRIDE];
                        uint32_t b1 = bk[gq * 8 * BSTRIDE + 4];
#pragma unroll
                        for (int ms = 0; ms < 4; ms++)
                            mma16816(d + (ms * 4 + gq) * 4,
                                     w9[2 * ms], w9[2 * ms + 1],
                                     w9[2 * ms + 1], w9[2 * ms + 2], b0, b1);
                    }
                }
            }
        }

        // ---- epilogue: power + permuted store ----
        size_t ob = ((size_t)(b * LL + t0 + mwarp + lq)) * (CC * RR);
#pragma unroll
        for (int ms = 0; ms < 4; ms++) {
#pragma unroll
            for (int gq = 0; gq < 4; gq++) {
                const float* dd = d + (ms * 4 + gq) * 4;
                float p0 = dd[0] * dd[0] + dd[1] * dd[1];
                float p1 = dd[2] * dd[2] + dd[3] * dd[3];
                out[ob + (size_t)(ms * 16) * (CC * RR) + rcol[gq]] = p0;
                out[ob + (size_t)(ms * 16 + 8) * (CC * RR) + rcol[gq]] = p1;
            }
        }

        g = gn;
    }
}

extern "C" void kernel_launch(void* const* d_in, const int* in_sizes, int n_in,
                              void* d_out, int out_size) {
    const float* x  = (const float*)d_in[0];
    const float* kV = (const float*)d_in[1];
    const float* sV = (const float*)d_in[2];
    float* out = (float*)d_out;

    cudaFuncSetAttribute(conv_kernel, cudaFuncAttributeMaxDynamicSharedMemorySize,
                         SMEM_BYTES);

    // 1) Gabor bank (sigma-sorted, bf16 hi/lo) + per-half level tables
    bank_kernel<<<256, 256>>>(kV, sV);

    // 2) persistent implicit-GEMM wavelet transform, 2 CTAs/SM overlap
    conv_kernel<<<NBLOCKS, NTHREADS, SMEM_BYTES>>>(x, out);
}

// round 12
// speedup vs baseline: 3.6221x; 1.1516x over previous
#include <cuda_runtime.h>
#include <cuda_bf16.h>
#include <math.h>
#include <stdint.h>

// Problem constants
#define BB 16
#define CC 8
#define LL 16384
#define RR 32

#define TM 256                 // t rows per CTA tile
#define NTILES 8192            // c-major: c=g>>10, b=(g>>6)&15, seg=g&63
#define NBLOCKS 304            // 2 CTAs per SM
#define NTHREADS 256           // 8 warps; warp = m64 x n32 (one n-half)

#define BSTRIDE 132            // uint32 words per B row (264 bf16, padded)

// SMEM offsets (bytes)
#define BH_OFF 0                         // B_hi: 64 rows * 132 words = 33792 B
#define BL_OFF 33792                     // B_lo
#define XW_OFF 67584                     // fp32 window: 544 floats (2176 B)
#define PEH_OFF (XW_OFF + 2176)          // even-pair hi: 272 words
#define POH_OFF (PEH_OFF + 1152)
#define PEL_OFF (POH_OFF + 1152)
#define POL_OFF (PEL_OFF + 1152)
#define SG_OFF  (POL_OFF + 1152)
#define SMEM_BYTES (SG_OFF + 16)         // ~74 KB -> 2 CTAs/SM

// Gabor bank, bf16 hi/lo, padded: row n (0..63) = 2*pos + (0=re,1=im), tap w
__device__ __align__(16) __nv_bfloat16 g_bh[CC][64 * 2 * BSTRIDE];
__device__ __align__(16) __nv_bfloat16 g_bl[CC][64 * 2 * BSTRIDE];
__device__ int   g_pr[CC][32];      // sorted pos -> actual output r
// Per-half level tables: [c][h]: .x/.y = kc order nibbles (in-half count desc),
// .z = cum[1..4] bytes (cum[l] = #kc with count >= l)
__device__ uint4 g_tab[CC][2];
__device__ unsigned int g_counter;

__global__ void bank_kernel(const float* __restrict__ kV, const float* __restrict__ sV) {
    int idx = blockIdx.x * blockDim.x + threadIdx.x;
    if (idx >= 65536) return;
    int f = idx >> 8, w = idx & 255;
    int c = f >> 5, j = f & 31;
    float k = kV[f], s = sV[f];

    // sort rank within channel, sigma DESC (pos 0 = largest sigma), tie by j
    int pos = 0;
    for (int j2 = 0; j2 < 32; j2++) {
        float s2 = sV[c * 32 + j2];
        pos += (s2 > s) || (s2 == s && j2 < j);
    }

    float phase = ((float)(-2.0 * M_PI / 256.0) * k) * (float)w;
    double sp, cp;
    sincos((double)phase, &sp, &cp);
    float nm = (float)w - 128.0f;
    float s2v = s * s;
    float inv2s2 = 1.0f / (2.0f * s2v);
    float coef = 1.0f / sqrtf(2.0f * (float)M_PI * s2v);
    float gauss = coef * expf(-inv2s2 * nm * nm);
    float fre = (float)cp * gauss, fim = (float)sp * gauss;

    __nv_bfloat16 h = __float2bfloat16(fre);
    __nv_bfloat16 l = __float2bfloat16(fre - __bfloat162float(h));
    g_bh[c][(2 * pos) * 264 + w] = h;
    g_bl[c][(2 * pos) * 264 + w] = l;
    h = __float2bfloat16(fim);
    l = __float2bfloat16(fim - __bfloat162float(h));
    g_bh[c][(2 * pos + 1) * 264 + w] = h;
    g_bl[c][(2 * pos + 1) * 264 + w] = l;

    if (w == 0) g_pr[c][pos] = 31 - j;   // reference reverses R
}

// Parallel per-channel truncation tables (was a 40us single-thread tail).
__global__ void table_kernel(const float* __restrict__ sV) {
    __shared__ float sg[32];
    __shared__ int kl[8], kh[8];
    int c = blockIdx.x;      // 0..7
    int j = threadIdx.x;     // 0..31
    float s = sV[c * 32 + j];
    int pos = 0;
    for (int j2 = 0; j2 < 32; j2++) {
        float s2 = sV[c * 32 + j2];
        pos += (s2 > s) || (s2 == s && j2 < j);
    }
    sg[pos] = s;             // sigma sorted descending
    __syncthreads();
    if (j < 8) {             // group gq support interval from its max sigma
        float D = 4.5f * sg[4 * j];
        int a = (int)floorf((128.0f - D) * (1.0f / 16.0f));
        int e = (int)floorf((128.0f + D) * (1.0f / 16.0f));
        kl[j] = a < 0 ? 0 : a;
        kh[j] = e > 15 ? 15 : e;
    }
    __syncthreads();
    if (j < 2) {             // per-half counting sort of kc by active count
        int cnt[16];
        for (int kc = 0; kc < 16; kc++) {
            int cn = 0;
            for (int gq = 4 * j; gq < 4 * j + 4; gq++)
                cn += (kl[gq] <= kc && kc <= kh[gq]);
            cnt[kc] = cn;
        }
        unsigned long long ord = 0ull;
        int cum[6];
        int ip = 0;
        for (int l2 = 4; l2 >= 1; l2--) {
            for (int kc = 0; kc < 16; kc++)
                if (cnt[kc] == l2) {
                    ord |= (unsigned long long)kc << (4 * ip);
                    ip++;
                }
            cum[l2] = ip;
        }
        uint4 tab;
        tab.x = (unsigned int)(ord & 0xFFFFFFFFull);
        tab.y = (unsigned int)(ord >> 32);
        tab.z = (unsigned int)cum[1] | ((unsigned int)cum[2] << 8) |
                ((unsigned int)cum[3] << 16) | ((unsigned int)cum[4] << 24);
        tab.w = 0;
        g_tab[c][j] = tab;
    }
    if (c == 0 && j == 0) g_counter = 0;
}

__device__ __forceinline__ uint32_t pack2(__nv_bfloat16 a, __nv_bfloat16 b) {
    __nv_bfloat162 t(a, b);
    return *reinterpret_cast<uint32_t*>(&t);
}

__device__ __forceinline__ void mma16816(float* d,
                                         uint32_t a0, uint32_t a1, uint32_t a2, uint32_t a3,
                                         uint32_t b0, uint32_t b1) {
    asm volatile(
        "mma.sync.aligned.m16n8k16.row.col.f32.bf16.bf16.f32 "
        "{%0,%1,%2,%3}, {%4,%5,%6,%7}, {%8,%9}, {%0,%1,%2,%3};"
        : "+f"(d[0]), "+f"(d[1]), "+f"(d[2]), "+f"(d[3])
        : "r"(a0), "r"(a1), "r"(a2), "r"(a3), "r"(b0), "r"(b1));
}

__global__ void __launch_bounds__(NTHREADS, 2)
conv_kernel(const float* __restrict__ x, float* __restrict__ out) {
    extern __shared__ unsigned char smem[];
    float* xw = (float*)(smem + XW_OFF);
    uint32_t* PEHw = (uint32_t*)(smem + PEH_OFF);
    uint32_t* POHw = (uint32_t*)(smem + POH_OFF);
    uint32_t* PELw = (uint32_t*)(smem + PEL_OFF);
    uint32_t* POLw = (uint32_t*)(smem + POL_OFF);
    const uint32_t* SW = (const uint32_t*)smem;     // word-indexed smem base
    unsigned int* sgp = (unsigned int*)(smem + SG_OFF);

    int tid  = threadIdx.x;
    int wid  = tid >> 5;
    int lane = tid & 31;
    int lq   = lane >> 2;     // 0..7
    int lr   = lane & 3;      // 0..3
    int half = wid & 1;       // n-half: groups 4*half .. 4*half+3
    int mwarp = (wid >> 1) * 64;
    int odd = lq & 1;
    int abase = (mwarp >> 1) + (lq >> 1) + lr;

    // 32-bit word offsets (register-lean addressing)
    int awH = (odd ? POH_OFF : PEH_OFF) / 4 + abase;
    int awL = (odd ? POL_OFF : PEL_OFF) / 4 + abase;
    int blH = BH_OFF / 4 + (4 * half) * 8 * BSTRIDE + lq * BSTRIDE + lr;
    int blL = BL_OFF / 4 + (4 * half) * 8 * BSTRIDE + lq * BSTRIDE + lr;

    if (tid == 0) sgp[0] = atomicAdd(&g_counter, 1u);
    __syncthreads();
    unsigned int g = sgp[0];

    // prefetch first tile's x window: xw[j] = x[b, t0-128+j, c], j in [0,544)
    float v0 = 0, v1 = 0;
    {
        unsigned int gc = (g < NTILES) ? g : 0u;
        int c2 = gc >> 10, b2 = (gc >> 6) & 15, t02 = (int)(gc & 63) << 8;
        const float* xb = x + (size_t)b2 * LL * CC + c2;
        int l = t02 - 128 + tid;
        v0 = (l >= 0 && l < LL) ? xb[(size_t)l * CC] : 0.0f;
        if (tid < 288) {
            int l1 = l + 256;
            v1 = (l1 >= 0 && l1 < LL) ? xb[(size_t)l1 * CC] : 0.0f;
        }
    }

    int cur_c = -1;
    unsigned long long ordv = 0ull;
    int cum1 = 0, cum2 = 0, cum3 = 0, cum4 = 0;
    int rcol[4];
    while (g < NTILES) {
        int c = g >> 10, b = (g >> 6) & 15, t0 = (int)(g & 63) << 8;

        __syncthreads();   // B1: previous tile's smem readers done

        if (c != cur_c) {  // stage B + per-channel tables
            const uint4* sH = (const uint4*)g_bh[c];
            const uint4* sL = (const uint4*)g_bl[c];
            uint4* dH = (uint4*)(smem + BH_OFF);
            uint4* dL = (uint4*)(smem + BL_OFF);
            for (int i = tid; i < 2112; i += NTHREADS) { dH[i] = sH[i]; dL[i] = sL[i]; }
            uint4 tab = g_tab[c][half];
            ordv = (unsigned long long)tab.x | ((unsigned long long)tab.y << 32);
            cum1 = (int)(tab.z & 255u);
            cum2 = (int)((tab.z >> 8) & 255u);
            cum3 = (int)((tab.z >> 16) & 255u);
            cum4 = (int)((tab.z >> 24) & 255u);
#pragma unroll
            for (int gq = 0; gq < 4; gq++)
                rcol[gq] = c * RR + g_pr[c][(4 * half + gq) * 4 + lr];
            cur_c = c;
        }

        // stage fp32 window
        xw[tid] = v0;
        if (tid < 288) xw[256 + tid] = v1;
        if (tid == 0) sgp[1] = atomicAdd(&g_counter, 1u);
        __syncthreads();   // mid: xw visible

        // build hi/lo even/odd bf16-pair arrays (264 entries)
        if (tid < 264) {
            float a0 = xw[2 * tid], a1 = xw[2 * tid + 1], a2 = xw[2 * tid + 2];
            __nv_bfloat16 h0 = __float2bfloat16(a0);
            __nv_bfloat16 l0 = __float2bfloat16(a0 - __bfloat162float(h0));
            __nv_bfloat16 h1 = __float2bfloat16(a1);
            __nv_bfloat16 l1 = __float2bfloat16(a1 - __bfloat162float(h1));
            __nv_bfloat16 h2 = __float2bfloat16(a2);
            __nv_bfloat16 l2 = __float2bfloat16(a2 - __bfloat162float(h2));
            PEHw[tid] = pack2(h0, h1); POHw[tid] = pack2(h1, h2);
            PELw[tid] = pack2(l0, l1); POLw[tid] = pack2(l1, l2);
        }
        __syncthreads();   // B2
        unsigned int gn = sgp[1];

        // prefetch next tile's x (hidden under the MMA mainloop)
        {
            unsigned int gc = (gn < NTILES) ? gn : 0u;
            int c2 = gc >> 10, b2 = (gc >> 6) & 15, t02 = (int)(gc & 63) << 8;
            const float* xb = x + (size_t)b2 * LL * CC + c2;
            int l = t02 - 128 + tid;
            v0 = (l >= 0 && l < LL) ? xb[(size_t)l * CC] : 0.0f;
            if (tid < 288) {
                int l1 = l + 256;
                v1 = (l1 >= 0 && l1 < LL) ? xb[(size_t)l1 * CC] : 0.0f;
            }
        }

        // ---- fused 3-pass hi/lo bf16 GEMM, per-half level-loop ----
        // Per kc: load A_hi once -> AH*BH + AH*BL; reload regs with A_lo ->
        // AL*BH. One kc decode instead of three; all acc indices compile-time.
        float d[64];
#pragma unroll
        for (int i = 0; i < 64; i++) d[i] = 0.0f;

#pragma unroll
        for (int lv = 4; lv >= 1; lv--) {
            int i0 = (lv == 4) ? 0 : ((lv == 3) ? cum4 : ((lv == 2) ? cum3 : cum2));
            int i1 = (lv == 4) ? cum4 : ((lv == 3) ? cum3 : ((lv == 2) ? cum2 : cum1));
#pragma unroll 1
            for (int idx = i0; idx < i1; idx++) {
                int kc = (int)((ordv >> (4 * idx)) & 15ull);
                int ah = awH + kc * 8;
                int bh = blH + kc * 8;
                int bls = blL + kc * 8;
                uint32_t w9[9];
#pragma unroll
                for (int u = 0; u < 9; u++) w9[u] = SW[ah + 4 * u];
#pragma unroll
                for (int gq = 0; gq < lv; gq++) {
                    uint32_t h0 = SW[bh + gq * 8 * BSTRIDE];
                    uint32_t h1 = SW[bh + gq * 8 * BSTRIDE + 4];
                    uint32_t l0 = SW[bls + gq * 8 * BSTRIDE];
                    uint32_t l1 = SW[bls + gq * 8 * BSTRIDE + 4];
#pragma unroll
                    for (int ms = 0; ms < 4; ms++)
                        mma16816(d + (ms * 4 + gq) * 4,
                                 w9[2 * ms], w9[2 * ms + 1],
                                 w9[2 * ms + 1], w9[2 * ms + 2], h0, h1);
#pragma unroll
                    for (int ms = 0; ms < 4; ms++)
                        mma16816(d + (ms * 4 + gq) * 4,
                                 w9[2 * ms], w9[2 * ms + 1],
                                 w9[2 * ms + 1], w9[2 * ms + 2], l0, l1);
                }
                int al = awL + kc * 8;
#pragma unroll
                for (int u = 0; u < 9; u++) w9[u] = SW[al + 4 * u];
#pragma unroll
                for (int gq = 0; gq < lv; gq++) {
                    uint32_t h0 = SW[bh + gq * 8 * BSTRIDE];
                    uint32_t h1 = SW[bh + gq * 8 * BSTRIDE + 4];
#pragma unroll
                    for (int ms = 0; ms < 4; ms++)
                        mma16816(d + (ms * 4 + gq) * 4,
                                 w9[2 * ms], w9[2 * ms + 1],
                                 w9[2 * ms + 1], w9[2 * ms + 2], h0, h1);
                }
            }
        }

        // ---- epilogue: power + permuted store ----
        size_t ob = ((size_t)(b * LL + t0 + mwarp + lq)) * (CC * RR);
#pragma unroll
        for (int ms = 0; ms < 4; ms++) {
#pragma unroll
            for (int gq = 0; gq < 4; gq++) {
                const float* dd = d + (ms * 4 + gq) * 4;
                float p0 = dd[0] * dd[0] + dd[1] * dd[1];
                float p1 = dd[2] * dd[2] + dd[3] * dd[3];
                out[ob + (size_t)(ms * 16) * (CC * RR) + rcol[gq]] = p0;
                out[ob + (size_t)(ms * 16 + 8) * (CC * RR) + rcol[gq]] = p1;
            }
        }

        g = gn;
    }
}

extern "C" void kernel_launch(void* const* d_in, const int* in_sizes, int n_in,
                              void* d_out, int out_size) {
    const float* x  = (const float*)d_in[0];
    const float* kV = (const float*)d_in[1];
    const float* sV = (const float*)d_in[2];
    float* out = (float*)d_out;

    cudaFuncSetAttribute(conv_kernel, cudaFuncAttributeMaxDynamicSharedMemorySize,
                         SMEM_BYTES);

    // 1) Gabor bank (sigma-sorted, bf16 hi/lo)
    bank_kernel<<<256, 256>>>(kV, sV);
    // 2) per-channel truncation tables + queue reset (parallel, ~2us)
    table_kernel<<<CC, 32>>>(sV);
    // 3) persistent implicit-GEMM wavelet transform, 2 CTAs/SM overlap
    conv_kernel<<<NBLOCKS, NTHREADS, SMEM_BYTES>>>(x, out);
}

// round 13
// speedup vs baseline: 6.3318x; 1.7481x over previous
#include <cuda_runtime.h>
#include <cuda_fp16.h>
#include <math.h>
#include <stdint.h>

// Problem constants
#define BB 16
#define CC 8
#define LL 16384
#define RR 32

#define TM 256                 // t rows per CTA tile
#define NTILES 8192            // c-major: c=g>>10, b=(g>>6)&15, seg=g&63
#define NBLOCKS 304            // 2 CTAs per SM
#define NTHREADS 256           // 8 warps; warp = m64 x n32 (one n-half)

#define BSTRIDE 132            // uint32 words per B row (264 fp16, padded)

// SMEM offsets (bytes)
#define BH_OFF 0                         // B: 64 rows * 132 words = 33792 B
#define XW_OFF 33792                     // fp32 window: 544 floats (2176 B)
#define PEH_OFF (XW_OFF + 2176)          // even-pair fp16: 272 words
#define POH_OFF (PEH_OFF + 1152)         // odd-pair fp16
#define SG_OFF  (POH_OFF + 1152)
#define SMEM_BYTES (SG_OFF + 16)         // ~38.3 KB -> 2 CTAs/SM easily

// Gabor bank, single fp16, padded: row n (0..63) = 2*pos + (0=re,1=im), tap w
__device__ __align__(16) __half g_bh[CC][64 * 2 * BSTRIDE];
__device__ int   g_pr[CC][32];      // sorted pos -> actual output r
// Per-half level tables: [c][h]: .x/.y = kc order nibbles (in-half count desc),
// .z = cum[1..4] bytes (cum[l] = #kc with count >= l)
__device__ uint4 g_tab[CC][2];
__device__ unsigned int g_counter;

__global__ void bank_kernel(const float* __restrict__ kV, const float* __restrict__ sV) {
    int idx = blockIdx.x * blockDim.x + threadIdx.x;
    if (idx >= 65536) return;
    int f = idx >> 8, w = idx & 255;
    int c = f >> 5, j = f & 31;
    float k = kV[f], s = sV[f];

    // sort rank within channel, sigma DESC (pos 0 = largest sigma), tie by j
    int pos = 0;
    for (int j2 = 0; j2 < 32; j2++) {
        float s2 = sV[c * 32 + j2];
        pos += (s2 > s) || (s2 == s && j2 < j);
    }

    float phase = ((float)(-2.0 * M_PI / 256.0) * k) * (float)w;
    double sp, cp;
    sincos((double)phase, &sp, &cp);
    float nm = (float)w - 128.0f;
    float s2v = s * s;
    float inv2s2 = 1.0f / (2.0f * s2v);
    float coef = 1.0f / sqrtf(2.0f * (float)M_PI * s2v);
    float gauss = coef * expf(-inv2s2 * nm * nm);
    float fre = (float)cp * gauss, fim = (float)sp * gauss;

    g_bh[c][(2 * pos) * 264 + w] = __float2half(fre);
    g_bh[c][(2 * pos + 1) * 264 + w] = __float2half(fim);

    if (w == 0) g_pr[c][pos] = 31 - j;   // reference reverses R
}

// Parallel per-channel truncation tables.
__global__ void table_kernel(const float* __restrict__ sV) {
    __shared__ float sg[32];
    __shared__ int kl[8], kh[8];
    int c = blockIdx.x;      // 0..7
    int j = threadIdx.x;     // 0..31
    float s = sV[c * 32 + j];
    int pos = 0;
    for (int j2 = 0; j2 < 32; j2++) {
        float s2 = sV[c * 32 + j2];
        pos += (s2 > s) || (s2 == s && j2 < j);
    }
    sg[pos] = s;             // sigma sorted descending
    __syncthreads();
    if (j < 8) {             // group gq support interval from its max sigma
        float D = 4.5f * sg[4 * j];
        int a = (int)floorf((128.0f - D) * (1.0f / 16.0f));
        int e = (int)floorf((128.0f + D) * (1.0f / 16.0f));
        kl[j] = a < 0 ? 0 : a;
        kh[j] = e > 15 ? 15 : e;
    }
    __syncthreads();
    if (j < 2) {             // per-half counting sort of kc by active count
        int cnt[16];
        for (int kc = 0; kc < 16; kc++) {
            int cn = 0;
            for (int gq = 4 * j; gq < 4 * j + 4; gq++)
                cn += (kl[gq] <= kc && kc <= kh[gq]);
            cnt[kc] = cn;
        }
        unsigned long long ord = 0ull;
        int cum[6];
        int ip = 0;
        for (int l2 = 4; l2 >= 1; l2--) {
            for (int kc = 0; kc < 16; kc++)
                if (cnt[kc] == l2) {
                    ord |= (unsigned long long)kc << (4 * ip);
                    ip++;
                }
            cum[l2] = ip;
        }
        uint4 tab;
        tab.x = (unsigned int)(ord & 0xFFFFFFFFull);
        tab.y = (unsigned int)(ord >> 32);
        tab.z = (unsigned int)cum[1] | ((unsigned int)cum[2] << 8) |
                ((unsigned int)cum[3] << 16) | ((unsigned int)cum[4] << 24);
        tab.w = 0;
        g_tab[c][j] = tab;
    }
    if (c == 0 && j == 0) g_counter = 0;
}

__device__ __forceinline__ uint32_t pack2h(__half a, __half b) {
    __half2 t(a, b);          // .x = a = low half = smaller k
    return *reinterpret_cast<uint32_t*>(&t);
}

__device__ __forceinline__ void mma16816(float* d,
                                         uint32_t a0, uint32_t a1, uint32_t a2, uint32_t a3,
                                         uint32_t b0, uint32_t b1) {
    asm volatile(
        "mma.sync.aligned.m16n8k16.row.col.f32.f16.f16.f32 "
        "{%0,%1,%2,%3}, {%4,%5,%6,%7}, {%8,%9}, {%0,%1,%2,%3};"
        : "+f"(d[0]), "+f"(d[1]), "+f"(d[2]), "+f"(d[3])
        : "r"(a0), "r"(a1), "r"(a2), "r"(a3), "r"(b0), "r"(b1));
}

__global__ void __launch_bounds__(NTHREADS, 2)
conv_kernel(const float* __restrict__ x, float* __restrict__ out) {
    extern __shared__ unsigned char smem[];
    float* xw = (float*)(smem + XW_OFF);
    uint32_t* PEHw = (uint32_t*)(smem + PEH_OFF);
    uint32_t* POHw = (uint32_t*)(smem + POH_OFF);
    const uint32_t* SW = (const uint32_t*)smem;     // word-indexed smem base
    unsigned int* sgp = (unsigned int*)(smem + SG_OFF);

    int tid  = threadIdx.x;
    int wid  = tid >> 5;
    int lane = tid & 31;
    int lq   = lane >> 2;     // 0..7
    int lr   = lane & 3;      // 0..3
    int half = wid & 1;       // n-half: groups 4*half .. 4*half+3
    int mwarp = (wid >> 1) * 64;
    int odd = lq & 1;
    int abase = (mwarp >> 1) + (lq >> 1) + lr;

    // 32-bit word offsets (register-lean addressing)
    int awH = (odd ? POH_OFF : PEH_OFF) / 4 + abase;
    int blH = BH_OFF / 4 + (4 * half) * 8 * BSTRIDE + lq * BSTRIDE + lr;

    if (tid == 0) sgp[0] = atomicAdd(&g_counter, 1u);
    __syncthreads();
    unsigned int g = sgp[0];

    // prefetch first tile's x window: xw[j] = x[b, t0-128+j, c], j in [0,544)
    float v0 = 0, v1 = 0;
    {
        unsigned int gc = (g < NTILES) ? g : 0u;
        int c2 = gc >> 10, b2 = (gc >> 6) & 15, t02 = (int)(gc & 63) << 8;
        const float* xb = x + (size_t)b2 * LL * CC + c2;
        int l = t02 - 128 + tid;
        v0 = (l >= 0 && l < LL) ? xb[(size_t)l * CC] : 0.0f;
        if (tid < 288) {
            int l1 = l + 256;
            v1 = (l1 >= 0 && l1 < LL) ? xb[(size_t)l1 * CC] : 0.0f;
        }
    }

    int cur_c = -1;
    unsigned long long ordv = 0ull;
    int cum1 = 0, cum2 = 0, cum3 = 0, cum4 = 0;
    int rcol[4];
    while (g < NTILES) {
        int c = g >> 10, b = (g >> 6) & 15, t0 = (int)(g & 63) << 8;

        __syncthreads();   // B1: previous tile's smem readers done

        if (c != cur_c) {  // stage B + per-channel tables
            const uint4* sH = (const uint4*)g_bh[c];
            uint4* dH = (uint4*)(smem + BH_OFF);
            for (int i = tid; i < 2112; i += NTHREADS) dH[i] = sH[i];
            uint4 tab = g_tab[c][half];
            ordv = (unsigned long long)tab.x | ((unsigned long long)tab.y << 32);
            cum1 = (int)(tab.z & 255u);
            cum2 = (int)((tab.z >> 8) & 255u);
            cum3 = (int)((tab.z >> 16) & 255u);
            cum4 = (int)((tab.z >> 24) & 255u);
#pragma unroll
            for (int gq = 0; gq < 4; gq++)
                rcol[gq] = c * RR + g_pr[c][(4 * half + gq) * 4 + lr];
            cur_c = c;
        }

        // stage fp32 window
        xw[tid] = v0;
        if (tid < 288) xw[256 + tid] = v1;
        if (tid == 0) sgp[1] = atomicAdd(&g_counter, 1u);
        __syncthreads();   // mid: xw visible

        // build fp16 even/odd pair arrays (264 entries)
        if (tid < 264) {
            float a0 = xw[2 * tid], a1 = xw[2 * tid + 1], a2 = xw[2 * tid + 2];
            __half h0 = __float2half(a0);
            __half h1 = __float2half(a1);
            __half h2 = __float2half(a2);
            PEHw[tid] = pack2h(h0, h1);
            POHw[tid] = pack2h(h1, h2);
        }
        __syncthreads();   // B2
        unsigned int gn = sgp[1];

        // prefetch next tile's x (hidden under the MMA mainloop)
        {
            unsigned int gc = (gn < NTILES) ? gn : 0u;
            int c2 = gc >> 10, b2 = (gc >> 6) & 15, t02 = (int)(gc & 63) << 8;
            const float* xb = x + (size_t)b2 * LL * CC + c2;
            int l = t02 - 128 + tid;
            v0 = (l >= 0 && l < LL) ? xb[(size_t)l * CC] : 0.0f;
            if (tid < 288) {
                int l1 = l + 256;
                v1 = (l1 >= 0 && l1 < LL) ? xb[(size_t)l1 * CC] : 0.0f;
            }
        }

        // ---- single-pass fp16 GEMM, per-half level-loop truncation ----
        // Level block lv: kc's where exactly lv of this warp's 4 n-groups are
        // active (nested: active = first lv). A loaded once per kc (9 words).
        float d[64];
#pragma unroll
        for (int i = 0; i < 64; i++) d[i] = 0.0f;

#pragma unroll
        for (int lv = 4; lv >= 1; lv--) {
            int i0 = (lv == 4) ? 0 : ((lv == 3) ? cum4 : ((lv == 2) ? cum3 : cum2));
            int i1 = (lv == 4) ? cum4 : ((lv == 3) ? cum3 : ((lv == 2) ? cum2 : cum1));
#pragma unroll 1
            for (int idx = i0; idx < i1; idx++) {
                int kc = (int)((ordv >> (4 * idx)) & 15ull);
                int ah = awH + kc * 8;
                int bh = blH + kc * 8;
                uint32_t w9[9];
#pragma unroll
                for (int u = 0; u < 9; u++) w9[u] = SW[ah + 4 * u];
#pragma unroll
                for (int gq = 0; gq < lv; gq++) {
                    uint32_t b0 = SW[bh + gq * 8 * BSTRIDE];
                    uint32_t b1 = SW[bh + gq * 8 * BSTRIDE + 4];
#pragma unroll
                    for (int ms = 0; ms < 4; ms++)
                        mma16816(d + (ms * 4 + gq) * 4,
                                 w9[2 * ms], w9[2 * ms + 1],
                                 w9[2 * ms + 1], w9[2 * ms + 2], b0, b1);
                }
            }
        }

        // ---- epilogue: power + permuted store ----
        size_t ob = ((size_t)(b * LL + t0 + mwarp + lq)) * (CC * RR);
#pragma unroll
        for (int ms = 0; ms < 4; ms++) {
#pragma unroll
            for (int gq = 0; gq < 4; gq++) {
                const float* dd = d + (ms * 4 + gq) * 4;
                float p0 = dd[0] * dd[0] + dd[1] * dd[1];
                float p1 = dd[2] * dd[2] + dd[3] * dd[3];
                out[ob + (size_t)(ms * 16) * (CC * RR) + rcol[gq]] = p0;
                out[ob + (size_t)(ms * 16 + 8) * (CC * RR) + rcol[gq]] = p1;
            }
        }

        g = gn;
    }
}

extern "C" void kernel_launch(void* const* d_in, const int* in_sizes, int n_in,
                              void* d_out, int out_size) {
    const float* x  = (const float*)d_in[0];
    const float* kV = (const float*)d_in[1];
    const float* sV = (const float*)d_in[2];
    float* out = (float*)d_out;

    cudaFuncSetAttribute(conv_kernel, cudaFuncAttributeMaxDynamicSharedMemorySize,
                         SMEM_BYTES);

    // 1) Gabor bank (sigma-sorted, single fp16)
    bank_kernel<<<256, 256>>>(kV, sV);
    // 2) per-channel truncation tables + queue reset (parallel)
    table_kernel<<<CC, 32>>>(sV);
    // 3) persistent implicit-GEMM wavelet transform (single-pass fp16)
    conv_kernel<<<NBLOCKS, NTHREADS, SMEM_BYTES>>>(x, out);
}